// round 5
// baseline (speedup 1.0000x reference)
#include <cuda_runtime.h>
#include <math.h>

// Problem constants
#define Bn   32
#define Nn   256
#define Hn   64
#define EPSf 1e-6f

// Table: KI intervals (KI+1 nodes) over [0, DMAX]
#define KI    512
#define DMAXf 20.0f

// Persistent-kernel shape: all blocks co-resident (128 <= 148 SMs, 1 block/SM)
#define NB 128
#define NT 1024

// Scratch (no allocations allowed -> __device__ globals)
__device__ float4   g_cf[KI];        // power-basis cubic coeffs of f  per interval
__device__ float4   g_cfp[KI];       // power-basis cubic coeffs of f' per interval
__device__ float    g_v[Bn * Nn * 3];
__device__ float    g_tr[Bn * Nn];
__device__ unsigned g_bar_cnt[2];    // zero-init; reset by last arriver
__device__ unsigned g_bar_gen[2];    // monotone across graph replays (snapshot-based)

// Replay-safe grid barrier: generation counter, last-arriver resets count.
// Safe because all NB blocks are guaranteed co-resident.
__device__ __forceinline__ void grid_barrier(int id)
{
    __syncthreads();
    if (threadIdx.x == 0) {
        __threadfence();                                   // publish my phase writes
        unsigned gen = atomicAdd(&g_bar_gen[id], 0u);      // snapshot BEFORE arriving
        unsigned tkt = atomicAdd(&g_bar_cnt[id], 1u);
        if (tkt == NB - 1) {
            atomicExch(&g_bar_cnt[id], 0u);                // all arrived; none read cnt now
            __threadfence();
            atomicAdd(&g_bar_gen[id], 1u);                 // release
        } else {
            while (atomicAdd(&g_bar_gen[id], 0u) == gen) { /* spin */ }
        }
        __threadfence();                                   // acquire others' writes
    }
    __syncthreads();
}

// Overflow-safe fast tanh: MUFU.EX2 + MUFU.RCP, ~7 instructions.
__device__ __forceinline__ float fast_tanh(float z)
{
    float az = fabsf(z);
    float e  = __expf(-2.f * az);
    float t  = __fdividef(1.f - e, 1.f + e);
    return copysignf(t, z);
}

// One pair's contribution: cubic lookup for f and f', accumulate field + trace.
__device__ __forceinline__ void pair_acc(float xi0, float xi1, float xi2,
                                         float xj0, float xj1, float xj2,
                                         bool self, float inv_step,
                                         float& c0, float& c1, float& c2, float& trt)
{
    float r0 = xi0 - xj0, r1 = xi1 - xj1, r2 = xi2 - xj2;
    float d2   = fmaf(r0, r0, fmaf(r1, r1, fmaf(r2, r2, EPSf)));
    float rinv = rsqrtf(d2);
    float d    = d2 * rinv;

    float u = fminf(d * inv_step, (float)KI - 0.001f);
    int   k = (int)u;
    float w = u - (float)k;

    float4 A  = g_cf[k];
    float4 Bc = g_cfp[k];
    float f  = fmaf(fmaf(fmaf(A.w,  w, A.z),  w, A.y),  w, A.x);
    float fp = fmaf(fmaf(fmaf(Bc.w, w, Bc.z), w, Bc.y), w, Bc.x);

    float mask = self ? 0.f : 1.f;
    float fm = f * mask;
    c0  = fmaf(r0, fm, c0);
    c1  = fmaf(r1, fm, c1);
    c2  = fmaf(r2, fm, c2);
    trt = fmaf(fmaf(fp * (d2 - EPSf), rinv, 3.f * f), mask, trt);
}

// ---------------------------------------------------------------------------
// Fused persistent kernel: table build -> barrier -> pairs -> barrier -> final
// ---------------------------------------------------------------------------
__global__ void __launch_bounds__(NT, 1)
fused_kernel(const float* __restrict__ t_in,
             const float* __restrict__ x,
             const float* __restrict__ W1,   // (2,64)
             const float* __restrict__ b1,   // (64)
             const float* __restrict__ W2,   // (64,64)
             const float* __restrict__ b2,   // (64)
             const float* __restrict__ W3,   // (64,1)
             const float* __restrict__ b3,   // (1)
             float*       __restrict__ out)
{
    const int tid = threadIdx.x;
    const int blk = blockIdx.x;

    __shared__ float  sW2[Hn * Hn];      // 16 KB
    __shared__ float4 sh1[5][Hn];        // layer-1 triples for 5 nodes
    __shared__ float4 s_node[6];         // (f, f', f'') at 5 nodes
    __shared__ float  s_red[5][2][3];    // slot x warp partials
    __shared__ float  sxs[Nn * 3];       // batch positions (phase B)
    __shared__ float  red2[8][4];        // finalize partials
    __shared__ float  fin[4];

    const float hstep    = DMAXf / (float)KI;
    const float inv_step = (float)KI / DMAXf;

    // =========================== Phase A: table ===========================
    // Block handles nodes [4*blk .. 4*blk+4] (1-node overlap) -> 4 intervals.
    {
        // stage W2 (1024 threads x 1 float4 = 4096 floats)
        reinterpret_cast<float4*>(sW2)[tid] =
            reinterpret_cast<const float4*>(W2)[tid];

        const int slot = tid >> 6;        // 0..15; slots 0..4 active
        const int p    = tid & 63;
        const int node = blk * 4 + slot;  // max 127*4+4 = 512 (= KI) OK
        const float t  = t_in[0];
        const float d  = (float)node * hstep;

        // layer-1 triple for unit l = p of this node
        if (slot < 5) {
            float w0 = W1[p];
            float z  = fmaf(d, w0, fmaf(t, W1[64 + p], b1[p]));
            float h1 = fast_tanh(z);
            float e1 = 1.f - h1 * h1;
            float gg  = e1 * w0;
            float ggd = -2.f * h1 * gg * w0;
            sh1[slot][p] = make_float4(h1, gg, ggd, 0.f);
        }
        __syncthreads();

        // layer-2 unit m = p of this node (all operands in smem)
        float pf = 0.f, pfp = 0.f, pfpp = 0.f;
        if (slot < 5) {
            float s  = b2[p];
            float sd = 0.f, sdd = 0.f;
#pragma unroll 8
            for (int l = 0; l < Hn; l++) {
                float  w2 = sW2[l * 64 + p];
                float4 hv = sh1[slot][l];
                s   = fmaf(w2, hv.x, s);
                sd  = fmaf(w2, hv.y, sd);
                sdd = fmaf(w2, hv.z, sdd);
            }
            float h2 = fast_tanh(s);
            float e2 = 1.f - h2 * h2;
            float w3 = W3[p];
            pf   = w3 * h2;
            pfp  = w3 * e2 * sd;
            pfpp = w3 * fmaf(-2.f * h2 * e2 * sd, sd, e2 * sdd);
        }

        const unsigned FULL = 0xffffffffu;
#pragma unroll
        for (int off = 16; off; off >>= 1) {
            pf   += __shfl_down_sync(FULL, pf,   off);
            pfp  += __shfl_down_sync(FULL, pfp,  off);
            pfpp += __shfl_down_sync(FULL, pfpp, off);
        }
        if (slot < 5 && (p & 31) == 0) {
            int ws = p >> 5;
            s_red[slot][ws][0] = pf;
            s_red[slot][ws][1] = pfp;
            s_red[slot][ws][2] = pfpp;
        }
        __syncthreads();
        if (slot < 5 && p == 0) {
            s_node[slot] = make_float4(
                s_red[slot][0][0] + s_red[slot][1][0] + b3[0],
                s_red[slot][0][1] + s_red[slot][1][1],
                s_red[slot][0][2] + s_red[slot][1][2], 0.f);
        }
        __syncthreads();

        // Hermite -> power basis per interval; threads 0..3 own one interval.
        if (tid < 4) {
            float4 n0 = s_node[tid];
            float4 n1 = s_node[tid + 1];
            int idx = blk * 4 + tid;
            // f: values (n.x), scaled slopes h*(n.y)
            float P0 = n0.x, P1 = n1.x, M0 = hstep * n0.y, M1 = hstep * n1.y;
            g_cf[idx] = make_float4(P0, M0,
                                    3.f * (P1 - P0) - 2.f * M0 - M1,
                                    2.f * (P0 - P1) + M0 + M1);
            // f': values (n.y), scaled slopes h*(n.z)
            float Q0 = n0.y, Q1 = n1.y, R0 = hstep * n0.z, R1 = hstep * n1.z;
            g_cfp[idx] = make_float4(Q0, R0,
                                     3.f * (Q1 - Q0) - 2.f * R0 - R1,
                                     2.f * (Q0 - Q1) + R0 + R1);
        }
    }

    grid_barrier(0);

    // =========================== Phase B: pairs ===========================
    // Block -> (batch b, 64-wide i-slab). 32 warps: warp w owns i = base+w
    // and i = base+32+w, sharing one j sweep.
    {
        const int b     = blk >> 2;
        const int ibase = (blk & 3) * 64;

        for (int idx = tid; idx < Nn * 3; idx += NT)
            sxs[idx] = x[b * Nn * 3 + idx];
        __syncthreads();

        const int w    = tid >> 5;
        const int lane = tid & 31;
        const int iA   = ibase + w;
        const int iB   = iA + 32;

        const float a0 = sxs[3 * iA + 0], a1 = sxs[3 * iA + 1], a2 = sxs[3 * iA + 2];
        const float e0 = sxs[3 * iB + 0], e1 = sxs[3 * iB + 1], e2 = sxs[3 * iB + 2];

        float cA0 = 0.f, cA1 = 0.f, cA2 = 0.f, tA = 0.f;
        float cB0 = 0.f, cB1 = 0.f, cB2 = 0.f, tB = 0.f;

#pragma unroll
        for (int jj = 0; jj < 8; jj++) {
            int j = jj * 32 + lane;
            float xj0 = sxs[3 * j + 0];
            float xj1 = sxs[3 * j + 1];
            float xj2 = sxs[3 * j + 2];
            pair_acc(a0, a1, a2, xj0, xj1, xj2, j == iA, inv_step, cA0, cA1, cA2, tA);
            pair_acc(e0, e1, e2, xj0, xj1, xj2, j == iB, inv_step, cB0, cB1, cB2, tB);
        }

        const unsigned FULL = 0xffffffffu;
#pragma unroll
        for (int off = 16; off; off >>= 1) {
            cA0 += __shfl_down_sync(FULL, cA0, off);
            cA1 += __shfl_down_sync(FULL, cA1, off);
            cA2 += __shfl_down_sync(FULL, cA2, off);
            tA  += __shfl_down_sync(FULL, tA,  off);
            cB0 += __shfl_down_sync(FULL, cB0, off);
            cB1 += __shfl_down_sync(FULL, cB1, off);
            cB2 += __shfl_down_sync(FULL, cB2, off);
            tB  += __shfl_down_sync(FULL, tB,  off);
        }
        if (lane == 0) {
            const float invNm1 = 1.f / (float)(Nn - 1);
            int rA = b * Nn + iA;
            int rB = b * Nn + iB;
            g_v[rA * 3 + 0] = cA0 * invNm1;
            g_v[rA * 3 + 1] = cA1 * invNm1;
            g_v[rA * 3 + 2] = cA2 * invNm1;
            g_tr[rA]        = tA  * invNm1;
            g_v[rB * 3 + 0] = cB0 * invNm1;
            g_v[rB * 3 + 1] = cB1 * invNm1;
            g_v[rB * 3 + 2] = cB2 * invNm1;
            g_tr[rB]        = tB  * invNm1;
        }
    }

    grid_barrier(1);

    // ========================= Phase C: finalize ==========================
    if (blk < Bn) {
        const int b = blk;
        float v0 = 0.f, v1 = 0.f, v2 = 0.f, tr = 0.f;
        if (tid < Nn) {
            int row = b * Nn + tid;
            v0 = g_v[row * 3 + 0];
            v1 = g_v[row * 3 + 1];
            v2 = g_v[row * 3 + 2];
            tr = g_tr[row];
        }

        float s0 = v0, s1 = v1, s2 = v2, s3 = tr;
        const unsigned FULL = 0xffffffffu;
#pragma unroll
        for (int off = 16; off; off >>= 1) {
            s0 += __shfl_down_sync(FULL, s0, off);
            s1 += __shfl_down_sync(FULL, s1, off);
            s2 += __shfl_down_sync(FULL, s2, off);
            s3 += __shfl_down_sync(FULL, s3, off);
        }
        int warp = tid >> 5, lane = tid & 31;
        if (warp < 8 && lane == 0) {
            red2[warp][0] = s0; red2[warp][1] = s1;
            red2[warp][2] = s2; red2[warp][3] = s3;
        }
        __syncthreads();
        if (tid == 0) {
            float x0 = 0.f, x1 = 0.f, x2 = 0.f, x3 = 0.f;
#pragma unroll
            for (int wi = 0; wi < 8; wi++) {
                x0 += red2[wi][0]; x1 += red2[wi][1];
                x2 += red2[wi][2]; x3 += red2[wi][3];
            }
            const float invN = 1.f / (float)Nn;
            fin[0] = x0 * invN;
            fin[1] = x1 * invN;
            fin[2] = x2 * invN;
            fin[3] = x3;
        }
        __syncthreads();

        if (tid < Nn) {
            out[b * (Nn * 3) + tid * 3 + 0] = v0 - fin[0];
            out[b * (Nn * 3) + tid * 3 + 1] = v1 - fin[1];
            out[b * (Nn * 3) + tid * 3 + 2] = v2 - fin[2];
        }
        if (tid == 0)
            out[Bn * Nn * 3 + b] = fin[3] * (1.f - 1.f / (float)Nn);
    }
}

// ---------------------------------------------------------------------------
extern "C" void kernel_launch(void* const* d_in, const int* in_sizes, int n_in,
                              void* d_out, int out_size)
{
    const float* t  = (const float*)d_in[0];
    const float* x  = (const float*)d_in[1];
    const float* W1 = (const float*)d_in[2];
    const float* b1 = (const float*)d_in[3];
    const float* W2 = (const float*)d_in[4];
    const float* b2 = (const float*)d_in[5];
    const float* W3 = (const float*)d_in[6];
    const float* b3 = (const float*)d_in[7];

    fused_kernel<<<NB, NT>>>(t, x, W1, b1, W2, b2, W3, b3, (float*)d_out);
}